// round 6
// baseline (speedup 1.0000x reference)
#include <cuda_runtime.h>
#include <cstdint>

// Problem constants: N=200000 nodes, D=256 features, G=512 graphs.
#define D 256
#define G 512
#define GG 8                   // graphs per block in GEMM
#define CT 64                  // columns per block-tile in GEMM

__device__ int   g_layout;         // 0 = int32 indices, 1 = int64 indices
__device__ float g_sum[G * D];     // pooled features
__device__ float g_hG[G * D];      // relu(sum @ W + b)  (final, bias applied)

__device__ __forceinline__ int load_idx(const int* __restrict__ raw, int i, int layout)
{
    return layout ? raw[2 * i] : raw[i];
}

// ---------------------------------------------------------------------------
// Kernel 1: zero g_sum (re-zeroed every graph replay) and detect index
// storage layout from the LAST 256 int32 words (batch_idx is sorted, so the
// tail holds the max values: int32 => odd words nonzero; int64 (<2^32) =>
// odd words zero, even nonzero; all-zero => either path is correct).
// ---------------------------------------------------------------------------
__global__ void k_init(const int* __restrict__ raw, int n)
{
    int i = blockIdx.x * blockDim.x + threadIdx.x;
    g_sum[i] = 0.0f;

    if (blockIdx.x == 0) {
        int w = n - 256 + threadIdx.x;
        int odd_nz = 0, even_nz = 0;
        if (w >= 0) {
            int v = raw[w];
            if (v != 0) {
                if (w & 1) odd_nz = 1; else even_nz = 1;
            }
        }
        int o = __syncthreads_or(odd_nz);
        int e = __syncthreads_or(even_nz);
        if (threadIdx.x == 0)
            g_layout = o ? 0 : (e ? 1 : 0);
    }
}

// ---------------------------------------------------------------------------
// Kernel 2: segment sum over sorted batch_idx. Block owns 256 contiguous
// rows; 64 column-quads x 4 row-stripes; register accumulation, atomic
// flush only on segment boundary. Evict-normal loads so the tail of h
// stays L2-resident for k_out's reverse pass.
// ---------------------------------------------------------------------------
__global__ void k_segsum(const float* __restrict__ h, const int* __restrict__ raw, int n)
{
    __shared__ int sidx[256];
    int layout = g_layout;
    int r0 = blockIdx.x * 256;
    {
        int r = r0 + threadIdx.x;
        sidx[threadIdx.x] = (r < n) ? load_idx(raw, r, layout) : -1;
    }
    __syncthreads();

    int tx = threadIdx.x & 63;
    int ty = threadIdx.x >> 6;

    float4 acc = make_float4(0.f, 0.f, 0.f, 0.f);
    int cur = -1;

    for (int rr = ty; rr < 256; rr += 4) {
        int row = r0 + rr;
        if (row >= n) break;
        int seg = sidx[rr];
        if (seg != cur) {
            if (cur >= 0) {
                float* dst = &g_sum[cur * D + tx * 4];
                atomicAdd(dst + 0, acc.x);
                atomicAdd(dst + 1, acc.y);
                atomicAdd(dst + 2, acc.z);
                atomicAdd(dst + 3, acc.w);
            }
            acc = make_float4(0.f, 0.f, 0.f, 0.f);
            cur = seg;
        }
        const float4 v = *reinterpret_cast<const float4*>(h + (size_t)row * D + tx * 4);
        acc.x += v.x; acc.y += v.y; acc.z += v.z; acc.w += v.w;
    }
    if (cur >= 0) {
        float* dst = &g_sum[cur * D + tx * 4];
        atomicAdd(dst + 0, acc.x);
        atomicAdd(dst + 1, acc.y);
        atomicAdd(dst + 2, acc.z);
        atomicAdd(dst + 3, acc.w);
    }
}

// ---------------------------------------------------------------------------
// Kernel 3: GEMM, no split-K, no atomics. grid = (G/GG, D/CT) = (64, 4)
// = 256 blocks. Block: GG=8 graphs x CT=64 columns x full K=256.
// 256 threads = 64 columns x 4 k-groups; each thread accumulates 8 graphs
// over 64 k's; 4-way smem reduction; bias + relu applied here, writing the
// FINISHED g_hG (k_out no longer touches b).
// W traffic: 64 KB/block x 256 blocks = 16 MB (L2-bound, ~2.5us).
// ---------------------------------------------------------------------------
__global__ void __launch_bounds__(256) k_gemm(const float* __restrict__ W,
                                              const float* __restrict__ b)
{
    __shared__ float s[GG][D];          // pooled rows, 8 KB
    __shared__ float s2[4][GG][CT];     // partials, 8 KB
    int g0 = blockIdx.x * GG;
    int c0 = blockIdx.y * CT;
    int t  = threadIdx.x;
    int col = t & (CT - 1);
    int kg  = t >> 6;                   // k-group 0..3

    // load 8 pooled rows (2048 floats) coalesced
    for (int j = t; j < GG * D; j += 256)
        s[j >> 8][j & (D - 1)] = g_sum[(g0 + (j >> 8)) * D + (j & (D - 1))];
    __syncthreads();

    float acc[GG];
#pragma unroll
    for (int r = 0; r < GG; r++) acc[r] = 0.0f;

    int kbase = kg * 64;
#pragma unroll 4
    for (int i = 0; i < 64; i++) {
        int k = kbase + i;
        float w = __ldg(&W[k * D + c0 + col]);
#pragma unroll
        for (int r = 0; r < GG; r++)
            acc[r] = fmaf(s[r][k], w, acc[r]);
    }

#pragma unroll
    for (int r = 0; r < GG; r++)
        s2[kg][r][col] = acc[r];
    __syncthreads();

    // 512 outputs, 2 per thread: reduce 4 partials, bias, relu, store
    for (int o = t; o < GG * CT; o += 256) {
        int r = o >> 6;
        int c = o & (CT - 1);
        float v = s2[0][r][c] + s2[1][r][c] + s2[2][r][c] + s2[3][r][c] + b[c0 + c];
        g_hG[(g0 + r) * D + c0 + c] = fmaxf(v, 0.0f);
    }
}

// ---------------------------------------------------------------------------
// Kernel 4: out = g_hG[seg] + h, rows in REVERSE order to harvest the L2
// tail left by k_segsum; misses use evict-first so the tail isn't
// displaced. 7 L1 accesses per thread (was 9 with bias loads).
// ---------------------------------------------------------------------------
__global__ void k_out(const float* __restrict__ h, const int* __restrict__ raw,
                      float* __restrict__ out, int n)
{
    int layout = g_layout;
    int gt = blockIdx.x * blockDim.x + threadIdx.x;   // one thread per 2 quads
    int ridx = gt >> 5;
    if (ridx >= n) return;
    int i = n - 1 - ridx;     // reverse row order
    int q = (gt & 31) * 2;
    int seg = load_idx(raw, i, layout);

    const float4* hp = reinterpret_cast<const float4*>(h + (size_t)i * D) + q;
    const float4 a0 = __ldcs(hp);
    const float4 a1 = __ldcs(hp + 1);
    const float4* vp = reinterpret_cast<const float4*>(g_hG + seg * D) + q;
    const float4 v0 = vp[0];
    const float4 v1 = vp[1];

    float4 r0, r1;
    r0.x = v0.x + a0.x;  r0.y = v0.y + a0.y;
    r0.z = v0.z + a0.z;  r0.w = v0.w + a0.w;
    r1.x = v1.x + a1.x;  r1.y = v1.y + a1.y;
    r1.z = v1.z + a1.z;  r1.w = v1.w + a1.w;

    float4* op = reinterpret_cast<float4*>(out + (size_t)i * D) + q;
    __stcs(op, r0);
    __stcs(op + 1, r1);
}

extern "C" void kernel_launch(void* const* d_in, const int* in_sizes, int n_in,
                              void* d_out, int out_size)
{
    const float* h   = (const float*)d_in[0];
    const int*   raw = (const int*)  d_in[1];
    const float* W   = (const float*)d_in[2];
    const float* b   = (const float*)d_in[3];
    float* out = (float*)d_out;

    const int n  = in_sizes[1];
    const int nb = (n + 255) / 256;

    k_init  <<<G * D / 256, 256>>>(raw, n);
    k_segsum<<<nb, 256>>>(h, raw, n);
    k_gemm  <<<dim3(G / GG, D / CT), 256>>>(W, b);
    {
        long long tt = (long long)n * 32;   // one thread per 2 float4
        int blocks = (int)((tt + 255) / 256);
        k_out<<<blocks, 256>>>(h, raw, out, n);
    }
}

// round 7
// speedup vs baseline: 1.1708x; 1.1708x over previous
#include <cuda_runtime.h>
#include <cstdint>

// Problem constants: N=200000 nodes, D=256 features, G=512 graphs.
#define D 256
#define G 512
#define GPB 16                 // graphs per block-tile in GEMM
#define KPB 16                 // k-values per block-slice in GEMM
#define RPB 128                // rows per block in segsum

__device__ int   g_layout;         // 0 = int32 indices, 1 = int64 indices
__device__ float g_sum[G * D];     // pooled features
__device__ float g_acc[G * D];     // split-K accumulator (pre-bias, pre-relu)
__device__ float g_hG[G * D];      // relu(g_acc + b)

__device__ __forceinline__ int load_idx(const int* __restrict__ raw, int i, int layout)
{
    return layout ? raw[2 * i] : raw[i];
}

// ---------------------------------------------------------------------------
// Kernel 1: zero g_sum/g_acc (every replay) and detect index storage layout
// from the LAST 256 int32 words (batch_idx sorted: int32 => odd words
// nonzero; int64 (<2^32) => odd zero, even nonzero; all-zero => either).
// ---------------------------------------------------------------------------
__global__ void k_init(const int* __restrict__ raw, int n)
{
    int i = blockIdx.x * blockDim.x + threadIdx.x;
    g_sum[i] = 0.0f;
    g_acc[i] = 0.0f;

    if (blockIdx.x == 0) {
        int w = n - 256 + threadIdx.x;
        int odd_nz = 0, even_nz = 0;
        if (w >= 0) {
            int v = raw[w];
            if (v != 0) {
                if (w & 1) odd_nz = 1; else even_nz = 1;
            }
        }
        int o = __syncthreads_or(odd_nz);
        int e = __syncthreads_or(even_nz);
        if (threadIdx.x == 0)
            g_layout = o ? 0 : (e ? 1 : 0);
    }
}

// ---------------------------------------------------------------------------
// Kernel 2: segment sum, MLP-batched. Block owns RPB=128 contiguous rows;
// 64 column-quads x 4 row-stripes (32 rows/thread). Rows processed in
// chunks of 8: the 8 independent float4 loads issue up-front (MLP=8), then
// the segment-boundary logic runs on registers. Atomic flush only on
// boundaries. Evict-normal loads keep h's tail in L2 for k_out's reverse
// pass.
// ---------------------------------------------------------------------------
__global__ void __launch_bounds__(256) k_segsum(const float* __restrict__ h,
                                                const int* __restrict__ raw, int n)
{
    __shared__ int sidx[RPB];
    int layout = g_layout;
    int r0 = blockIdx.x * RPB;
    if (threadIdx.x < RPB) {
        int r = r0 + threadIdx.x;
        sidx[threadIdx.x] = (r < n) ? load_idx(raw, r, layout) : -1;
    }
    __syncthreads();

    int tx = threadIdx.x & 63;
    int ty = threadIdx.x >> 6;

    float4 acc = make_float4(0.f, 0.f, 0.f, 0.f);
    int cur = -1;

#pragma unroll
    for (int base = 0; base < RPB; base += 32) {
        // batch: 8 independent loads in flight
        float4 v[8];
#pragma unroll
        for (int j = 0; j < 8; j++) {
            int row = r0 + base + ty + j * 4;
            if (row < n)
                v[j] = *reinterpret_cast<const float4*>(h + (size_t)row * D + tx * 4);
            else
                v[j] = make_float4(0.f, 0.f, 0.f, 0.f);
        }
        // segment logic on registers
#pragma unroll
        for (int j = 0; j < 8; j++) {
            int rr = base + ty + j * 4;
            if (r0 + rr >= n) break;
            int seg = sidx[rr];
            if (seg != cur) {
                if (cur >= 0) {
                    float* dst = &g_sum[cur * D + tx * 4];
                    atomicAdd(dst + 0, acc.x);
                    atomicAdd(dst + 1, acc.y);
                    atomicAdd(dst + 2, acc.z);
                    atomicAdd(dst + 3, acc.w);
                }
                acc = make_float4(0.f, 0.f, 0.f, 0.f);
                cur = seg;
            }
            acc.x += v[j].x; acc.y += v[j].y; acc.z += v[j].z; acc.w += v[j].w;
        }
    }
    if (cur >= 0) {
        float* dst = &g_sum[cur * D + tx * 4];
        atomicAdd(dst + 0, acc.x);
        atomicAdd(dst + 1, acc.y);
        atomicAdd(dst + 2, acc.z);
        atomicAdd(dst + 3, acc.w);
    }
}

// ---------------------------------------------------------------------------
// Kernel 3: split-K GEMM (R4 form, measured 7.9us). grid (32,16) = 512
// blocks; thread t owns column t for GPB graphs over KPB k's; scalar
// atomic accumulate into g_acc.
// ---------------------------------------------------------------------------
__global__ void __launch_bounds__(256) k_gemm_splitk(const float* __restrict__ W)
{
    __shared__ float s[GPB][KPB];
    int g0 = blockIdx.x * GPB;
    int k0 = blockIdx.y * KPB;
    int t  = threadIdx.x;

    float w[KPB];
#pragma unroll
    for (int kk = 0; kk < KPB; kk++)
        w[kk] = __ldg(&W[(k0 + kk) * D + t]);

    {
        int r  = t >> 4;
        int kk = t & 15;
        s[r][kk] = g_sum[(g0 + r) * D + (k0 + kk)];
    }
    __syncthreads();

    float acc[GPB];
#pragma unroll
    for (int r = 0; r < GPB; r++) acc[r] = 0.0f;

#pragma unroll
    for (int kk = 0; kk < KPB; kk++) {
#pragma unroll
        for (int r = 0; r < GPB; r++)
            acc[r] = fmaf(s[r][kk], w[kk], acc[r]);
    }

#pragma unroll
    for (int r = 0; r < GPB; r++)
        atomicAdd(&g_acc[(g0 + r) * D + t], acc[r]);
}

// ---------------------------------------------------------------------------
// Kernel 4: tiny epilogue, g_hG = relu(g_acc + b). 512 KB, L2-resident.
// ---------------------------------------------------------------------------
__global__ void k_bias(const float* __restrict__ b)
{
    int i = (blockIdx.x * blockDim.x + threadIdx.x) * 4;   // float4 granularity
    float4 v = *reinterpret_cast<float4*>(&g_acc[i]);
    const float4 bb = *reinterpret_cast<const float4*>(b + (i & (D - 1)));
    float4 r;
    r.x = fmaxf(v.x + bb.x, 0.0f);
    r.y = fmaxf(v.y + bb.y, 0.0f);
    r.z = fmaxf(v.z + bb.z, 0.0f);
    r.w = fmaxf(v.w + bb.w, 0.0f);
    *reinterpret_cast<float4*>(&g_hG[i]) = r;
}

// ---------------------------------------------------------------------------
// Kernel 5: out = g_hG[seg] + h (lean form, measured 62.9us). Reverse row
// order harvests the L2 tail left by k_segsum; misses evict-first.
// ---------------------------------------------------------------------------
__global__ void k_out(const float* __restrict__ h, const int* __restrict__ raw,
                      float* __restrict__ out, int n)
{
    int layout = g_layout;
    int gt = blockIdx.x * blockDim.x + threadIdx.x;   // one thread per 2 quads
    int ridx = gt >> 5;
    if (ridx >= n) return;
    int i = n - 1 - ridx;     // reverse row order
    int q = (gt & 31) * 2;
    int seg = load_idx(raw, i, layout);

    const float4* hp = reinterpret_cast<const float4*>(h + (size_t)i * D) + q;
    const float4 a0 = __ldcs(hp);
    const float4 a1 = __ldcs(hp + 1);
    const float4* vp = reinterpret_cast<const float4*>(g_hG + seg * D) + q;
    const float4 v0 = vp[0];
    const float4 v1 = vp[1];

    float4 r0, r1;
    r0.x = v0.x + a0.x;  r0.y = v0.y + a0.y;
    r0.z = v0.z + a0.z;  r0.w = v0.w + a0.w;
    r1.x = v1.x + a1.x;  r1.y = v1.y + a1.y;
    r1.z = v1.z + a1.z;  r1.w = v1.w + a1.w;

    float4* op = reinterpret_cast<float4*>(out + (size_t)i * D) + q;
    __stcs(op, r0);
    __stcs(op + 1, r1);
}

extern "C" void kernel_launch(void* const* d_in, const int* in_sizes, int n_in,
                              void* d_out, int out_size)
{
    const float* h   = (const float*)d_in[0];
    const int*   raw = (const int*)  d_in[1];
    const float* W   = (const float*)d_in[2];
    const float* b   = (const float*)d_in[3];
    float* out = (float*)d_out;

    const int n  = in_sizes[1];
    const int nbs = (n + RPB - 1) / RPB;

    k_init  <<<G * D / 256, 256>>>(raw, n);
    k_segsum<<<nbs, 256>>>(h, raw, n);
    k_gemm_splitk<<<dim3(G / GPB, D / KPB), 256>>>(W);
    k_bias  <<<G * D / 4 / 256, 256>>>(b);
    {
        long long tt = (long long)n * 32;   // one thread per 2 float4
        int blocks = (int)((tt + 255) / 256);
        k_out<<<blocks, 256>>>(h, raw, out, n);
    }
}